// round 2
// baseline (speedup 1.0000x reference)
#include <cuda_runtime.h>
#include <math.h>

// Problem constants
#define BQ   4
#define LQ   513
#define DM   768
#define DI   1536
#define DSs  16
#define DRk  48
#define BL   (BQ*LQ)          // 2052
#define BLDM (BL*DM)          // 1,575,936
#define BLDI (BL*DI)          // 3,149,568
#define XZSZ (BL*2*DI)        // 6,299,136
#define DBL80 (BL*80)         // 164,160
#define XPSZ (BQ*512*256)     // 524,288

// Scratch (static device buffers — no allocation allowed)
__device__ __align__(256) float g_h  [BLDM];
__device__ __align__(256) float g_res[BLDM];
__device__ __align__(256) float g_xn [BLDM];
__device__ __align__(256) float g_xz [XZSZ];
__device__ __align__(256) float g_c  [2*BLDI];
__device__ __align__(256) float g_dt [2*BLDI];
__device__ __align__(256) float g_dbl[2*DBL80];
__device__ __align__(256) float g_y  [BLDI];
__device__ __align__(256) float g_xp [XPSZ];

// ---------------------------------------------------------------------------
// Generic register-blocked SGEMM:  C[m][n] = sum_k A[m][k] * B[n][k]  (+bias)
// A: M x K (lda), B: N x K (ldb)  -> "NT" layout, both K-contiguous.
// batch via gridDim.z = nbatch*ksplit ; ksplit>1 => atomicAdd partials.
// EPI: 0 = none, 1 = softplus (only with ksplit==1)
// ---------------------------------------------------------------------------
template<int BM,int BN,int BK,int TM,int TN,int EPI>
__global__ void __launch_bounds__(256) sgemm_nt(
    const float* __restrict__ Ag, int lda, size_t aStr,
    const float* __restrict__ Bg, int ldb, size_t bStr,
    float*       __restrict__ Cg, int ldc, size_t cStr,
    int M, int N, int K,
    const float* __restrict__ bias, size_t biasStr,
    int ksplit)
{
    const int bz    = blockIdx.z;
    const int batch = bz / ksplit;
    const int ks    = bz - batch*ksplit;
    const float* A = Ag + batch*aStr;
    const float* B = Bg + batch*bStr;
    float*       C = Cg + batch*cStr;
    const int kchunk = K / ksplit;
    const int k0     = ks * kchunk;

    const int row0 = blockIdx.y * BM;
    const int col0 = blockIdx.x * BN;

    __shared__ float As[BK][BM+4];
    __shared__ float Bs[BK][BN+4];

    const int tid = threadIdx.x;
    const int NT  = BN / TN;
    const int tx  = tid % NT;
    const int ty  = tid / NT;

    float acc[TM][TN];
    #pragma unroll
    for (int i=0;i<TM;i++)
        #pragma unroll
        for (int j=0;j<TN;j++) acc[i][j] = 0.f;

    const int KQ    = BK/4;
    const int lr0   = tid / KQ;
    const int lk    = (tid % KQ) * 4;
    const int RSTEP = 256 / KQ;

    for (int kb = k0; kb < k0 + kchunk; kb += BK) {
        #pragma unroll
        for (int r = lr0; r < BM; r += RSTEP) {
            float4 v = make_float4(0.f,0.f,0.f,0.f);
            int ar = row0 + r;
            if (ar < M) v = *(const float4*)(A + (size_t)ar*lda + kb + lk);
            As[lk+0][r]=v.x; As[lk+1][r]=v.y; As[lk+2][r]=v.z; As[lk+3][r]=v.w;
        }
        #pragma unroll
        for (int r = lr0; r < BN; r += RSTEP) {
            float4 v = make_float4(0.f,0.f,0.f,0.f);
            int br_ = col0 + r;
            if (br_ < N) v = *(const float4*)(B + (size_t)br_*ldb + kb + lk);
            Bs[lk+0][r]=v.x; Bs[lk+1][r]=v.y; Bs[lk+2][r]=v.z; Bs[lk+3][r]=v.w;
        }
        __syncthreads();
        #pragma unroll
        for (int kk=0; kk<BK; kk++) {
            float af[TM], bf[TN];
            #pragma unroll
            for (int i=0;i<TM;i+=4) *(float4*)&af[i] = *(const float4*)&As[kk][ty*TM+i];
            #pragma unroll
            for (int j=0;j<TN;j+=4) *(float4*)&bf[j] = *(const float4*)&Bs[kk][tx*TN+j];
            #pragma unroll
            for (int i=0;i<TM;i++)
                #pragma unroll
                for (int j=0;j<TN;j++)
                    acc[i][j] += af[i]*bf[j];
        }
        __syncthreads();
    }

    #pragma unroll
    for (int i=0;i<TM;i++) {
        int r = row0 + ty*TM + i;
        if (r >= M) continue;
        #pragma unroll
        for (int j=0;j<TN;j++) {
            int cc = col0 + tx*TN + j;
            if (cc >= N) continue;
            float v = acc[i][j];
            if (ksplit > 1) {
                atomicAdd(&C[(size_t)r*ldc + cc], v);
            } else {
                if (bias) v += bias[batch*biasStr + cc];
                if (EPI == 1) v = (v > 15.f) ? v : log1pf(expf(v));
                C[(size_t)r*ldc + cc] = v;
            }
        }
    }
}

// ---------------------------------------------------------------------------
// Patch gather: x(B,128,1024) -> xp(B,512,256)
// ---------------------------------------------------------------------------
__global__ void patch_gather(const float* __restrict__ x)
{
    int idx = blockIdx.x*256 + threadIdx.x;
    if (idx >= XPSZ) return;
    int inner = idx & 255;
    int p     = (idx >> 8) & 511;
    int b     = idx >> 17;
    int f = p >> 6, t = p & 63;
    int i = inner >> 4, j = inner & 15;
    g_xp[idx] = x[(size_t)b*131072 + (size_t)(f*16+i)*1024 + (t*16+j)];
}

// tok assemble: cls + pos, patches + pos (patch gemm already in g_xn)
__global__ void assemble_tok(const float* __restrict__ cls,
                             const float* __restrict__ pos)
{
    int idx = blockIdx.x*256 + threadIdx.x;
    if (idx >= BLDM) return;
    int m = idx % DM;
    int l = (idx / DM) % LQ;
    int b = idx / (DM*LQ);
    float v = (l == 0) ? cls[m] : g_xn[((size_t)b*512 + (l-1))*DM + m];
    g_h[idx] = v + pos[(size_t)l*DM + m];
}

// ---------------------------------------------------------------------------
// res += h ; xn = rmsnorm(res) * ln_w      (one block per token row)
// ---------------------------------------------------------------------------
__global__ void resnorm_kernel(const float* __restrict__ lnw)
{
    int r = blockIdx.x;
    int tid = threadIdx.x;
    size_t base = (size_t)r * DM;
    float v[3];
    float ss = 0.f;
    #pragma unroll
    for (int q=0;q<3;q++) {
        int i = tid + q*256;
        float t = g_res[base+i] + g_h[base+i];
        g_res[base+i] = t;
        v[q] = t;
        ss += t*t;
    }
    #pragma unroll
    for (int o=16;o;o>>=1) ss += __shfl_xor_sync(0xffffffffu, ss, o);
    __shared__ float sred[8];
    __shared__ float sscale;
    if ((tid & 31) == 0) sred[tid>>5] = ss;
    __syncthreads();
    if (tid == 0) {
        float t = 0.f;
        #pragma unroll
        for (int w=0;w<8;w++) t += sred[w];
        sscale = rsqrtf(t/(float)DM + 1e-5f);
    }
    __syncthreads();
    float sc = sscale;
    #pragma unroll
    for (int q=0;q<3;q++) {
        int i = tid + q*256;
        g_xn[base+i] = v[q]*sc*lnw[i];
    }
}

// ---------------------------------------------------------------------------
// Depthwise causal conv (K=4) + SiLU, with branch-1 sequence reversal.
// Reads u = g_xz[..., :DI], writes g_c[br][b][l][d].
// ---------------------------------------------------------------------------
__global__ void conv_silu(const float* __restrict__ cw,   // [2][DI][4]
                          const float* __restrict__ cb)   // [2][DI]
{
    size_t idx = (size_t)blockIdx.x*256 + threadIdx.x;
    if (idx >= (size_t)2*BLDI) return;
    int d  = (int)(idx % DI);
    size_t t1 = idx / DI;
    int l  = (int)(t1 % LQ);
    int t2 = (int)(t1 / LQ);
    int b  = t2 % BQ;
    int br = t2 / BQ;
    const float* w = cw + ((size_t)br*DI + d)*4;
    float s = cb[(size_t)br*DI + d];
    #pragma unroll
    for (int k=0;k<4;k++) {
        int j = l - 3 + k;
        if (j >= 0) {
            int pj = br ? (512 - j) : j;
            s += w[k] * g_xz[((size_t)b*LQ + pj)*(2*DI) + d];
        }
    }
    g_c[idx] = s / (1.f + __expf(-s));
}

// ---------------------------------------------------------------------------
// Selective-scan. One thread per (branch, b, channel d); 16 states in regs.
// Software-pipelined loads (dt/u/z coalesced; B/C rows broadcast, float4).
// Output: atomicAdd(0.5 * gated y) into g_y at un-reversed position.
// ---------------------------------------------------------------------------
__global__ void __launch_bounds__(128) ssm_scan_kernel(
    const float* __restrict__ a_log, const float* __restrict__ dd, int lyr)
{
    const int br = blockIdx.z;
    const int b  = blockIdx.y;
    const int d  = blockIdx.x*128 + threadIdx.x;

    const float* __restrict__ cC   = g_c  + ((size_t)(br*BQ+b))*LQ*DI + d;
    const float* __restrict__ dtC  = g_dt + ((size_t)(br*BQ+b))*LQ*DI + d;
    const float* __restrict__ dblC = g_dbl + (size_t)br*DBL80 + (size_t)b*LQ*80;
    const float* __restrict__ zC   = g_xz + (size_t)b*LQ*(2*DI) + DI + d;
    float*       __restrict__ yC   = g_y  + (size_t)b*LQ*DI + d;

    float A[16], h[16];
    size_t ab = (((size_t)lyr*2 + br)*DI + d)*16;
    #pragma unroll
    for (int s=0;s<16;s++) { A[s] = -__expf(a_log[ab+s]); h[s] = 0.f; }
    const float Dd = dd[((size_t)lyr*2 + br)*DI + d];

    // prologue: load step 0
    float n_dt = dtC[0];
    float n_u  = cC[0];
    float n_z  = zC[(size_t)(br ? 512 : 0)*(2*DI)];
    float4 nB[4], nC[4];
    {
        const float4* rb = (const float4*)(dblC + 48);
        #pragma unroll
        for (int q=0;q<4;q++) { nB[q] = rb[q]; nC[q] = rb[4+q]; }
    }

    for (int l = 0; l < LQ; l++) {
        float dtv = n_dt, uv = n_u, zv = n_z;
        float Bb[16], Cc[16];
        #pragma unroll
        for (int q=0;q<4;q++) { *(float4*)&Bb[4*q] = nB[q]; *(float4*)&Cc[4*q] = nC[q]; }

        if (l + 1 < LQ) {                       // prefetch next step
            size_t off = (size_t)(l+1)*DI;
            n_dt = dtC[off];
            n_u  = cC[off];
            int zl = br ? (512-(l+1)) : (l+1);
            n_z  = zC[(size_t)zl*(2*DI)];
            const float4* rb = (const float4*)(dblC + (size_t)(l+1)*80 + 48);
            #pragma unroll
            for (int q=0;q<4;q++) { nB[q] = rb[q]; nC[q] = rb[4+q]; }
        }

        float du = dtv*uv;
        float yv = 0.f;
        #pragma unroll
        for (int s=0;s<16;s++) {
            h[s] = __expf(dtv*A[s])*h[s] + du*Bb[s];
            yv  += h[s]*Cc[s];
        }
        float sg   = zv / (1.f + __expf(-zv));
        float outv = (yv + uv*Dd) * sg;
        int ol = br ? (512 - l) : l;
        atomicAdd(yC + (size_t)ol*DI, 0.5f*outv);
    }
}

// ---------------------------------------------------------------------------
// Final: layer_norm((res + h)[:, 0]) -> out (4 x 768)
// ---------------------------------------------------------------------------
__global__ void final_ln(const float* __restrict__ fw,
                         const float* __restrict__ fb,
                         float* __restrict__ out)
{
    int b = blockIdx.x;
    int tid = threadIdx.x;
    size_t base = (size_t)b*LQ*DM;   // row l=0
    float v[3];
    float s = 0.f;
    #pragma unroll
    for (int q=0;q<3;q++) {
        int i = tid + q*256;
        float t = g_res[base+i] + g_h[base+i];
        v[q] = t;
        s += t;
    }
    __shared__ float sred[8];
    __shared__ float sval;
    #pragma unroll
    for (int o=16;o;o>>=1) s += __shfl_xor_sync(0xffffffffu, s, o);
    if ((tid&31)==0) sred[tid>>5] = s;
    __syncthreads();
    if (tid==0) { float t=0.f; for(int w=0;w<8;w++) t+=sred[w]; sval = t/(float)DM; }
    __syncthreads();
    float mean = sval;
    float vv = 0.f;
    #pragma unroll
    for (int q=0;q<3;q++) { float dv = v[q]-mean; vv += dv*dv; }
    #pragma unroll
    for (int o=16;o;o>>=1) vv += __shfl_xor_sync(0xffffffffu, vv, o);
    __syncthreads();
    if ((tid&31)==0) sred[tid>>5] = vv;
    __syncthreads();
    if (tid==0) { float t=0.f; for(int w=0;w<8;w++) t+=sred[w]; sval = rsqrtf(t/(float)DM + 1e-5f); }
    __syncthreads();
    float inv = sval;
    #pragma unroll
    for (int q=0;q<3;q++) {
        int i = tid + q*256;
        out[(size_t)b*DM + i] = (v[q]-mean)*inv*fw[i] + fb[i];
    }
}

// ---------------------------------------------------------------------------
extern "C" void kernel_launch(void* const* d_in, const int* in_sizes, int n_in,
                              void* d_out, int out_size)
{
    (void)in_sizes; (void)n_in; (void)out_size;
    const float* x       = (const float*)d_in[0];
    const float* patch_w = (const float*)d_in[1];
    const float* patch_b = (const float*)d_in[2];
    const float* cls     = (const float*)d_in[3];
    const float* pos     = (const float*)d_in[4];
    const float* ln_w    = (const float*)d_in[5];
    const float* w_in    = (const float*)d_in[6];
    const float* conv_w  = (const float*)d_in[7];
    const float* conv_b  = (const float*)d_in[8];
    const float* w_x     = (const float*)d_in[9];
    const float* w_dt    = (const float*)d_in[10];
    const float* b_dt    = (const float*)d_in[11];
    const float* a_log   = (const float*)d_in[12];
    const float* dd      = (const float*)d_in[13];
    const float* w_out   = (const float*)d_in[14];
    const float* fn_w    = (const float*)d_in[15];
    const float* fn_b    = (const float*)d_in[16];
    float* out = (float*)d_out;

    float *p_h, *p_res, *p_xn, *p_xz, *p_c, *p_dt, *p_dbl, *p_y, *p_xp;
    cudaGetSymbolAddress((void**)&p_h,   g_h);
    cudaGetSymbolAddress((void**)&p_res, g_res);
    cudaGetSymbolAddress((void**)&p_xn,  g_xn);
    cudaGetSymbolAddress((void**)&p_xz,  g_xz);
    cudaGetSymbolAddress((void**)&p_c,   g_c);
    cudaGetSymbolAddress((void**)&p_dt,  g_dt);
    cudaGetSymbolAddress((void**)&p_dbl, g_dbl);
    cudaGetSymbolAddress((void**)&p_y,   g_y);
    cudaGetSymbolAddress((void**)&p_xp,  g_xp);

    // patch embed: gather -> gemm(2048x768x256, +patch_b) -> assemble(+cls,+pos)
    patch_gather<<<XPSZ/256, 256>>>(x);
    sgemm_nt<128,128,8,8,8,0><<<dim3(6,16,1),256>>>(
        p_xp,256,0,  patch_w,256,0,  p_xn,DM,0,
        2048, DM, 256,  patch_b, 0,  1);
    assemble_tok<<<BLDM/256, 256>>>(cls, pos);
    cudaMemsetAsync(p_res, 0, (size_t)BLDM*sizeof(float));

    for (int lyr = 0; lyr < 24; lyr++) {
        // res += h ; xn = rmsnorm(res)*ln_w
        resnorm_kernel<<<BL,256>>>(ln_w + (size_t)lyr*DM);

        // xz = xn @ w_in^T   (2052 x 3072 x 768)
        sgemm_nt<128,128,8,8,8,0><<<dim3(24,17,1),256>>>(
            p_xn,DM,0,  w_in + (size_t)lyr*2*DI*DM, DM,0,
            p_xz,2*DI,0,  BL, 2*DI, DM,  nullptr,0,  1);

        // conv + silu (both branches, branch-1 reversed)
        conv_silu<<<(unsigned)(((size_t)2*BLDI + 255)/256),256>>>(
            conv_w + (size_t)lyr*2*DI*4,  conv_b + (size_t)lyr*2*DI);

        // dbl = c @ w_x^T   (2052 x 80 x 1536)  split-K=8, batched over branches
        cudaMemsetAsync(p_dbl, 0, (size_t)2*DBL80*sizeof(float));
        sgemm_nt<64,64,16,4,4,0><<<dim3(2,33,16),256>>>(
            p_c, DI, (size_t)BLDI,
            w_x + (size_t)lyr*2*80*DI, DI, (size_t)80*DI,
            p_dbl, 80, (size_t)DBL80,
            BL, 80, DI,  nullptr,0,  8);

        // dt = softplus(dbl[:, :48] @ w_dt^T + b_dt)   (2052 x 1536 x 48)
        sgemm_nt<128,128,8,8,8,1><<<dim3(12,17,2),256>>>(
            p_dbl, 80, (size_t)DBL80,
            w_dt + (size_t)lyr*2*DI*DRk, DRk, (size_t)DI*DRk,
            p_dt, DI, (size_t)BLDI,
            BL, DI, DRk,
            b_dt + (size_t)lyr*2*DI, (size_t)DI,  1);

        // selective scan both branches -> g_y (pre-zeroed, atomic combine)
        cudaMemsetAsync(p_y, 0, (size_t)BLDI*sizeof(float));
        ssm_scan_kernel<<<dim3(12,4,2),128>>>(a_log, dd, lyr);

        // h = y @ w_out^T   (2052 x 768 x 1536)
        sgemm_nt<128,128,8,8,8,0><<<dim3(6,17,1),256>>>(
            p_y, DI, 0,
            w_out + (size_t)lyr*DM*DI, DI, 0,
            p_h, DM, 0,
            BL, DM, DI,  nullptr,0,  1);
    }

    final_ln<<<4,256>>>(fn_w, fn_b, out);
}

// round 5
// speedup vs baseline: 1.7062x; 1.7062x over previous
#include <cuda_runtime.h>
#include <cuda_bf16.h>
#include <math.h>
#include <stdint.h>

// Problem constants
#define BQ   4
#define LQ   513
#define DM   768
#define DI   1536
#define DSs  16
#define DRk  48
#define BL   (BQ*LQ)          // 2052
#define BLDM (BL*DM)
#define BLDI (BL*DI)
#define XZSZ (BL*2*DI)
#define DBL80 (BL*80)
#define XPSZ (BQ*512*256)

// fp32 scratch
__device__ __align__(256) float g_h  [BLDM];
__device__ __align__(256) float g_res[BLDM];
__device__ __align__(256) float g_xn [BLDM];
__device__ __align__(256) float g_xz [XZSZ];
__device__ __align__(256) float g_c  [2*BLDI];
__device__ __align__(256) float g_dt [2*BLDI];
__device__ __align__(256) float g_dbl[2*DBL80];
__device__ __align__(256) float g_y  [BLDI];
__device__ __align__(256) float g_xp [XPSZ];

// bf16 split-extended operands.  A rows: [hi|lo|hi]; B rows: [hi|hi|lo]
// dot(Aext,Bext) = hi*hi + lo*hi + hi*lo  (error ~2^-18)
#define WE_IN_SZ  ((size_t)24*3072*2304)
#define WE_OUT_SZ ((size_t)24*768*4608)
#define WE_X_SZ   ((size_t)24*2*80*4608)
#define WE_DT_SZ  ((size_t)24*2*1536*192)
#define AE_XN_SZ  ((size_t)2052*2304)
#define AE_C_SZ   ((size_t)4104*4608)
#define AE_DT_SZ  ((size_t)4104*192)
#define AE_Y_SZ   ((size_t)2052*4608)
__device__ __align__(256) __nv_bfloat16 g_we_in [WE_IN_SZ];
__device__ __align__(256) __nv_bfloat16 g_we_out[WE_OUT_SZ];
__device__ __align__(256) __nv_bfloat16 g_we_x  [WE_X_SZ];
__device__ __align__(256) __nv_bfloat16 g_we_dt [WE_DT_SZ];
__device__ __align__(256) __nv_bfloat16 g_ae_xn [AE_XN_SZ];
__device__ __align__(256) __nv_bfloat16 g_ae_c  [AE_C_SZ];
__device__ __align__(256) __nv_bfloat16 g_ae_dt [AE_DT_SZ];
__device__ __align__(256) __nv_bfloat16 g_ae_y  [AE_Y_SZ];

// ---------------------------------------------------------------------------
__device__ __forceinline__ uint32_t smem_u32(const void* p){
    uint32_t a;
    asm("{ .reg .u64 t; cvta.to.shared.u64 t, %1; cvt.u32.u64 %0, t; }" : "=r"(a) : "l"(p));
    return a;
}
__device__ __forceinline__ void cp16(uint32_t dst, const void* src, bool valid){
    int sz = valid ? 16 : 0;
    asm volatile("cp.async.ca.shared.global [%0], [%1], 16, %2;"
                 :: "r"(dst), "l"(src), "r"(sz) : "memory");
}
#define LDM_X4(r, addr) \
    asm volatile("ldmatrix.sync.aligned.m8n8.x4.shared.b16 {%0,%1,%2,%3}, [%4];" \
        : "=r"((r)[0]), "=r"((r)[1]), "=r"((r)[2]), "=r"((r)[3]) : "r"(addr))
__device__ __forceinline__ void mma16816(float* d, const uint32_t* a, uint32_t b0, uint32_t b1){
    asm volatile(
      "mma.sync.aligned.m16n8k16.row.col.f32.bf16.bf16.f32 "
      "{%0,%1,%2,%3}, {%4,%5,%6,%7}, {%8,%9}, {%0,%1,%2,%3};"
      : "+f"(d[0]), "+f"(d[1]), "+f"(d[2]), "+f"(d[3])
      : "r"(a[0]), "r"(a[1]), "r"(a[2]), "r"(a[3]), "r"(b0), "r"(b1));
}

// ---------------------------------------------------------------------------
// Split-extend converter.  side=0 (A): [hi|lo|hi]; side=1 (B): [hi|hi|lo].
// ---------------------------------------------------------------------------
__global__ void cvt_ext(const float* __restrict__ src, __nv_bfloat16* __restrict__ dst,
                        int rows, int K, int Kpad, int srcStride, int side)
{
    int idx = blockIdx.x*256 + threadIdx.x;
    int total = rows*Kpad;
    if (idx >= total) return;
    int r = idx / Kpad, k = idx - r*Kpad;
    float x = (k < K) ? src[(size_t)r*srcStride + k] : 0.f;
    __nv_bfloat16 hi = __float2bfloat16_rn(x);
    __nv_bfloat16 lo = __float2bfloat16_rn(x - __bfloat162float(hi));
    __nv_bfloat16* row = dst + (size_t)r*3*Kpad;
    row[k]          = hi;
    row[Kpad+k]     = side ? hi : lo;
    row[2*Kpad+k]   = side ? lo : hi;
}

// ---------------------------------------------------------------------------
// HMMA bf16 GEMM: C[m][n] = sum_k Aext[m][k]*Bext[n][k]
// 128x128 tile, 8 warps (each 64x32), BK=64, cp.async double-buffered.
// epi: 0 none, 1 softplus(+bias). ksplit>1 -> atomicAdd (no epi).
// ---------------------------------------------------------------------------
#define AROW 144               // bytes per smem row (64 bf16 + 16B pad)
#define ABUF (128*AROW)        // 18432
#define STG  (2*ABUF)          // 36864 per stage
#define GEMM_SMEM (2*STG)      // 73728

__global__ void __launch_bounds__(256,2) gemm_mma(
    const __nv_bfloat16* __restrict__ Ag, int ldaE, size_t aStr,
    const __nv_bfloat16* __restrict__ Bg, int ldbE, size_t bStr,
    float* __restrict__ Cg, int ldc, size_t cStr,
    int M, int N, int Kext,
    const float* __restrict__ bias, int biasStr,
    int ksplit, int epi)
{
    extern __shared__ char smem[];
    const int tid  = threadIdx.x;
    const int lane = tid & 31;
    const int wid  = tid >> 5;
    uint32_t sbase = smem_u32(smem);

    const int bz    = blockIdx.z;
    const int batch = bz / ksplit;
    const int ks    = bz - batch*ksplit;
    const __nv_bfloat16* A = Ag + (size_t)batch*aStr;
    const __nv_bfloat16* B = Bg + (size_t)batch*bStr;
    float* C = Cg + (size_t)batch*cStr;
    const int row0 = blockIdx.y*128;
    const int col0 = blockIdx.x*128;
    const int kTot = Kext / ksplit;
    const int kstart = ks * kTot;
    const int nch = kTot / 64;

    // stage loader: 128 rows x 64 bf16 per operand, 16B chunks
    auto load_stage = [&](int ci, int buf){
        int kb = kstart + ci*64;
        uint32_t aD = sbase + buf*STG;
        uint32_t bD = aD + ABUF;
        #pragma unroll
        for (int q = 0; q < 4; q++) {
            int c = tid + q*256;
            int r = c >> 3, g = c & 7;
            bool av = (row0 + r) < M;
            cp16(aD + r*AROW + g*16,
                 A + (size_t)(av ? row0 + r : 0)*ldaE + kb + g*8, av);
            bool bv = (col0 + r) < N;
            cp16(bD + r*AROW + g*16,
                 B + (size_t)(bv ? col0 + r : 0)*ldbE + kb + g*8, bv);
        }
        asm volatile("cp.async.commit_group;" ::: "memory");
    };

    float acc[4][4][4];
    #pragma unroll
    for (int i=0;i<4;i++) for (int j=0;j<4;j++) for (int q=0;q<4;q++) acc[i][j][q]=0.f;

    const int wm = (wid >> 2) * 64;
    const int wn = (wid & 3) * 32;

    load_stage(0, 0);
    for (int ci = 0; ci < nch; ci++) {
        if (ci + 1 < nch) load_stage(ci+1, (ci+1)&1);
        if (ci + 1 < nch) asm volatile("cp.async.wait_group 1;" ::: "memory");
        else              asm volatile("cp.async.wait_group 0;" ::: "memory");
        __syncthreads();

        uint32_t aB = sbase + (ci&1)*STG;
        uint32_t bB = aB + ABUF;
        #pragma unroll
        for (int k16 = 0; k16 < 4; k16++) {
            int k0 = k16*16;
            uint32_t afr[4][4];
            #pragma unroll
            for (int mi = 0; mi < 4; mi++) {
                uint32_t addr = aB + (uint32_t)(wm + mi*16 + (lane & 15))*AROW
                              + (uint32_t)(k0 + ((lane >> 4) << 3))*2;
                LDM_X4(afr[mi], addr);
            }
            uint32_t bfr[2][4];
            #pragma unroll
            for (int nj = 0; nj < 2; nj++) {
                uint32_t addr = bB + (uint32_t)(wn + nj*16 + (lane & 7) + ((lane >> 4) << 3))*AROW
                              + (uint32_t)(k0 + (((lane >> 3) & 1) << 3))*2;
                LDM_X4(bfr[nj], addr);
            }
            #pragma unroll
            for (int mi = 0; mi < 4; mi++)
                #pragma unroll
                for (int ni = 0; ni < 4; ni++)
                    mma16816(acc[mi][ni], afr[mi],
                             bfr[ni>>1][(ni&1)*2], bfr[ni>>1][(ni&1)*2+1]);
        }
        __syncthreads();
    }

    // epilogue
    #pragma unroll
    for (int mi = 0; mi < 4; mi++) {
        #pragma unroll
        for (int ni = 0; ni < 4; ni++) {
            float* d = acc[mi][ni];
            int gc = col0 + wn + ni*8 + 2*(lane & 3);
            int gr = row0 + wm + mi*16 + (lane >> 2);
            #pragma unroll
            for (int hf = 0; hf < 2; hf++) {
                int r = gr + hf*8;
                float v0 = d[hf*2+0], v1 = d[hf*2+1];
                if (r < M) {
                    if (ksplit > 1) {
                        if (gc   < N) atomicAdd(&C[(size_t)r*ldc + gc],   v0);
                        if (gc+1 < N) atomicAdd(&C[(size_t)r*ldc + gc+1], v1);
                    } else {
                        if (bias) {
                            v0 += bias[(size_t)batch*biasStr + gc];
                            v1 += bias[(size_t)batch*biasStr + gc + 1];
                        }
                        if (epi == 1) {
                            v0 = (v0 > 15.f) ? v0 : log1pf(expf(v0));
                            v1 = (v1 > 15.f) ? v1 : log1pf(expf(v1));
                        }
                        *(float2*)&C[(size_t)r*ldc + gc] = make_float2(v0, v1);
                    }
                }
            }
        }
    }
}

// ---------------------------------------------------------------------------
// FFMA SGEMM (patch embed only)
// ---------------------------------------------------------------------------
template<int BM,int BN,int BK,int TM,int TN>
__global__ void __launch_bounds__(256) sgemm_nt(
    const float* __restrict__ A, int lda,
    const float* __restrict__ B, int ldb,
    float*       __restrict__ C, int ldc,
    int M, int N, int K, const float* __restrict__ bias)
{
    const int row0 = blockIdx.y * BM;
    const int col0 = blockIdx.x * BN;
    __shared__ float As[BK][BM+4];
    __shared__ float Bs[BK][BN+4];
    const int tid = threadIdx.x;
    const int NT  = BN / TN;
    const int tx  = tid % NT, ty = tid / NT;
    float acc[TM][TN];
    #pragma unroll
    for (int i=0;i<TM;i++) for (int j=0;j<TN;j++) acc[i][j]=0.f;
    const int KQ = BK/4, lr0 = tid/KQ, lk = (tid%KQ)*4, RS = 256/KQ;
    for (int kb=0; kb<K; kb+=BK) {
        #pragma unroll
        for (int r=lr0;r<BM;r+=RS){
            float4 v=make_float4(0,0,0,0);
            if (row0+r<M) v=*(const float4*)(A+(size_t)(row0+r)*lda+kb+lk);
            As[lk+0][r]=v.x;As[lk+1][r]=v.y;As[lk+2][r]=v.z;As[lk+3][r]=v.w;
        }
        #pragma unroll
        for (int r=lr0;r<BN;r+=RS){
            float4 v=make_float4(0,0,0,0);
            if (col0+r<N) v=*(const float4*)(B+(size_t)(col0+r)*ldb+kb+lk);
            Bs[lk+0][r]=v.x;Bs[lk+1][r]=v.y;Bs[lk+2][r]=v.z;Bs[lk+3][r]=v.w;
        }
        __syncthreads();
        #pragma unroll
        for (int kk=0;kk<BK;kk++){
            float af[TM], bf[TN];
            #pragma unroll
            for (int i=0;i<TM;i+=4) *(float4*)&af[i]=*(const float4*)&As[kk][ty*TM+i];
            #pragma unroll
            for (int j=0;j<TN;j+=4) *(float4*)&bf[j]=*(const float4*)&Bs[kk][tx*TN+j];
            #pragma unroll
            for (int i=0;i<TM;i++) for (int j=0;j<TN;j++) acc[i][j]+=af[i]*bf[j];
        }
        __syncthreads();
    }
    #pragma unroll
    for (int i=0;i<TM;i++){
        int r=row0+ty*TM+i; if(r>=M) continue;
        #pragma unroll
        for (int j=0;j<TN;j++){
            int c=col0+tx*TN+j; if(c>=N) continue;
            float v=acc[i][j];
            if (bias) v+=bias[c];
            C[(size_t)r*ldc+c]=v;
        }
    }
}

// ---------------------------------------------------------------------------
__global__ void patch_gather(const float* __restrict__ x)
{
    int idx = blockIdx.x*256 + threadIdx.x;
    if (idx >= XPSZ) return;
    int inner = idx & 255;
    int p     = (idx >> 8) & 511;
    int b     = idx >> 17;
    int f = p >> 6, t = p & 63;
    int i = inner >> 4, j = inner & 15;
    g_xp[idx] = x[(size_t)b*131072 + (size_t)(f*16+i)*1024 + (t*16+j)];
}

__global__ void assemble_tok(const float* __restrict__ cls,
                             const float* __restrict__ pos)
{
    int idx = blockIdx.x*256 + threadIdx.x;
    if (idx >= BLDM) return;
    int m = idx % DM;
    int l = (idx / DM) % LQ;
    int b = idx / (DM*LQ);
    float v = (l == 0) ? cls[m] : g_xn[((size_t)b*512 + (l-1))*DM + m];
    g_h[idx] = v + pos[(size_t)l*DM + m];
}

__global__ void resnorm_kernel(const float* __restrict__ lnw)
{
    int r = blockIdx.x;
    int tid = threadIdx.x;
    size_t base = (size_t)r * DM;
    float v[3];
    float ss = 0.f;
    #pragma unroll
    for (int q=0;q<3;q++) {
        int i = tid + q*256;
        float t = g_res[base+i] + g_h[base+i];
        g_res[base+i] = t;
        v[q] = t;
        ss += t*t;
    }
    #pragma unroll
    for (int o=16;o;o>>=1) ss += __shfl_xor_sync(0xffffffffu, ss, o);
    __shared__ float sred[8];
    __shared__ float sscale;
    if ((tid & 31) == 0) sred[tid>>5] = ss;
    __syncthreads();
    if (tid == 0) {
        float t = 0.f;
        #pragma unroll
        for (int w=0;w<8;w++) t += sred[w];
        sscale = rsqrtf(t/(float)DM + 1e-5f);
    }
    __syncthreads();
    float sc = sscale;
    #pragma unroll
    for (int q=0;q<3;q++) {
        int i = tid + q*256;
        g_xn[base+i] = v[q]*sc*lnw[i];
    }
}

__global__ void conv_silu(const float* __restrict__ cw,
                          const float* __restrict__ cb)
{
    size_t idx = (size_t)blockIdx.x*256 + threadIdx.x;
    if (idx >= (size_t)2*BLDI) return;
    int d  = (int)(idx % DI);
    size_t t1 = idx / DI;
    int l  = (int)(t1 % LQ);
    int t2 = (int)(t1 / LQ);
    int b  = t2 % BQ;
    int br = t2 / BQ;
    const float* w = cw + ((size_t)br*DI + d)*4;
    float s = cb[(size_t)br*DI + d];
    #pragma unroll
    for (int k=0;k<4;k++) {
        int j = l - 3 + k;
        if (j >= 0) {
            int pj = br ? (512 - j) : j;
            s += w[k] * g_xz[((size_t)b*LQ + pj)*(2*DI) + d];
        }
    }
    g_c[idx] = s / (1.f + __expf(-s));
}

__global__ void __launch_bounds__(128) ssm_scan_kernel(
    const float* __restrict__ a_log, const float* __restrict__ dd, int lyr)
{
    const int br = blockIdx.z;
    const int b  = blockIdx.y;
    const int d  = blockIdx.x*128 + threadIdx.x;

    const float* __restrict__ cC   = g_c  + ((size_t)(br*BQ+b))*LQ*DI + d;
    const float* __restrict__ dtC  = g_dt + ((size_t)(br*BQ+b))*LQ*DI + d;
    const float* __restrict__ dblC = g_dbl + (size_t)br*DBL80 + (size_t)b*LQ*80;
    const float* __restrict__ zC   = g_xz + (size_t)b*LQ*(2*DI) + DI + d;
    float*       __restrict__ yC   = g_y  + (size_t)b*LQ*DI + d;

    float A[16], h[16];
    size_t ab = (((size_t)lyr*2 + br)*DI + d)*16;
    #pragma unroll
    for (int s=0;s<16;s++) { A[s] = -__expf(a_log[ab+s]); h[s] = 0.f; }
    const float Dd = dd[((size_t)lyr*2 + br)*DI + d];

    float n_dt = dtC[0];
    float n_u  = cC[0];
    float n_z  = zC[(size_t)(br ? 512 : 0)*(2*DI)];
    float4 nB[4], nC[4];
    {
        const float4* rb = (const float4*)(dblC + 48);
        #pragma unroll
        for (int q=0;q<4;q++) { nB[q] = rb[q]; nC[q] = rb[4+q]; }
    }

    for (int l = 0; l < LQ; l++) {
        float dtv = n_dt, uv = n_u, zv = n_z;
        float Bb[16], Cc[16];
        #pragma unroll
        for (int q=0;q<4;q++) { *(float4*)&Bb[4*q] = nB[q]; *(float4*)&Cc[4*q] = nC[q]; }

        if (l + 1 < LQ) {
            size_t off = (size_t)(l+1)*DI;
            n_dt = dtC[off];
            n_u  = cC[off];
            int zl = br ? (512-(l+1)) : (l+1);
            n_z  = zC[(size_t)zl*(2*DI)];
            const float4* rb = (const float4*)(dblC + (size_t)(l+1)*80 + 48);
            #pragma unroll
            for (int q=0;q<4;q++) { nB[q] = rb[q]; nC[q] = rb[4+q]; }
        }

        float du = dtv*uv;
        float yv = 0.f;
        #pragma unroll
        for (int s=0;s<16;s++) {
            h[s] = __expf(dtv*A[s])*h[s] + du*Bb[s];
            yv  += h[s]*Cc[s];
        }
        float sg   = zv / (1.f + __expf(-zv));
        float outv = (yv + uv*Dd) * sg;
        int ol = br ? (512 - l) : l;
        atomicAdd(yC + (size_t)ol*DI, 0.5f*outv);
    }
}

__global__ void final_ln(const float* __restrict__ fw,
                         const float* __restrict__ fb,
                         float* __restrict__ out)
{
    int b = blockIdx.x;
    int tid = threadIdx.x;
    size_t base = (size_t)b*LQ*DM;
    float v[3];
    float s = 0.f;
    #pragma unroll
    for (int q=0;q<3;q++) {
        int i = tid + q*256;
        float t = g_res[base+i] + g_h[base+i];
        v[q] = t;
        s += t;
    }
    __shared__ float sred[8];
    __shared__ float sval;
    #pragma unroll
    for (int o=16;o;o>>=1) s += __shfl_xor_sync(0xffffffffu, s, o);
    if ((tid&31)==0) sred[tid>>5] = s;
    __syncthreads();
    if (tid==0) { float t=0.f; for(int w=0;w<8;w++) t+=sred[w]; sval = t/(float)DM; }
    __syncthreads();
    float mean = sval;
    float vv = 0.f;
    #pragma unroll
    for (int q=0;q<3;q++) { float dv = v[q]-mean; vv += dv*dv; }
    #pragma unroll
    for (int o=16;o;o>>=1) vv += __shfl_xor_sync(0xffffffffu, vv, o);
    __syncthreads();
    if ((tid&31)==0) sred[tid>>5] = vv;
    __syncthreads();
    if (tid==0) { float t=0.f; for(int w=0;w<8;w++) t+=sred[w]; sval = rsqrtf(t/(float)DM + 1e-5f); }
    __syncthreads();
    float inv = sval;
    #pragma unroll
    for (int q=0;q<3;q++) {
        int i = tid + q*256;
        out[(size_t)b*DM + i] = (v[q]-mean)*inv*fw[i] + fb[i];
    }
}

// ---------------------------------------------------------------------------
static inline unsigned cdiv(size_t a, unsigned b){ return (unsigned)((a + b - 1) / b); }

extern "C" void kernel_launch(void* const* d_in, const int* in_sizes, int n_in,
                              void* d_out, int out_size)
{
    (void)in_sizes; (void)n_in; (void)out_size;
    const float* x       = (const float*)d_in[0];
    const float* patch_w = (const float*)d_in[1];
    const float* patch_b = (const float*)d_in[2];
    const float* cls     = (const float*)d_in[3];
    const float* pos     = (const float*)d_in[4];
    const float* ln_w    = (const float*)d_in[5];
    const float* w_in    = (const float*)d_in[6];
    const float* conv_w  = (const float*)d_in[7];
    const float* conv_b  = (const float*)d_in[8];
    const float* w_x     = (const float*)d_in[9];
    const float* w_dt    = (const float*)d_in[10];
    const float* b_dt    = (const float*)d_in[11];
    const float* a_log   = (const float*)d_in[12];
    const float* dd      = (const float*)d_in[13];
    const float* w_out   = (const float*)d_in[14];
    const float* fn_w    = (const float*)d_in[15];
    const float* fn_b    = (const float*)d_in[16];
    float* out = (float*)d_out;

    float *p_res, *p_xn, *p_xz, *p_c, *p_dt, *p_dbl, *p_y, *p_xp, *p_h;
    cudaGetSymbolAddress((void**)&p_h,   g_h);
    cudaGetSymbolAddress((void**)&p_res, g_res);
    cudaGetSymbolAddress((void**)&p_xn,  g_xn);
    cudaGetSymbolAddress((void**)&p_xz,  g_xz);
    cudaGetSymbolAddress((void**)&p_c,   g_c);
    cudaGetSymbolAddress((void**)&p_dt,  g_dt);
    cudaGetSymbolAddress((void**)&p_dbl, g_dbl);
    cudaGetSymbolAddress((void**)&p_y,   g_y);
    cudaGetSymbolAddress((void**)&p_xp,  g_xp);
    __nv_bfloat16 *we_in, *we_out, *we_x, *we_dt, *ae_xn, *ae_c, *ae_dt, *ae_y;
    cudaGetSymbolAddress((void**)&we_in,  g_we_in);
    cudaGetSymbolAddress((void**)&we_out, g_we_out);
    cudaGetSymbolAddress((void**)&we_x,   g_we_x);
    cudaGetSymbolAddress((void**)&we_dt,  g_we_dt);
    cudaGetSymbolAddress((void**)&ae_xn,  g_ae_xn);
    cudaGetSymbolAddress((void**)&ae_c,   g_ae_c);
    cudaGetSymbolAddress((void**)&ae_dt,  g_ae_dt);
    cudaGetSymbolAddress((void**)&ae_y,   g_ae_y);

    cudaFuncSetAttribute(gemm_mma, cudaFuncAttributeMaxDynamicSharedMemorySize, GEMM_SMEM);

    // ---- Weight split-extension (once per launch, inside graph) ----
    cvt_ext<<<cdiv((size_t)24*3072*768,256),256>>>(w_in,  we_in,  24*3072, 768,  768,  768,  1);
    cvt_ext<<<cdiv((size_t)24*768*1536,256),256>>>(w_out, we_out, 24*768,  1536, 1536, 1536, 1);
    cvt_ext<<<cdiv((size_t)24*2*80*1536,256),256>>>(w_x,  we_x,   24*2*80, 1536, 1536, 1536, 1);
    cvt_ext<<<cdiv((size_t)24*2*1536*64,256),256>>>(w_dt, we_dt,  24*2*1536, 48, 64,   48,   1);

    // ---- patch embed ----
    patch_gather<<<XPSZ/256, 256>>>(x);
    sgemm_nt<128,128,8,8,8><<<dim3(6,16,1),256>>>(p_xp,256, patch_w,256, p_xn,DM,
                                                  2048, DM, 256, patch_b);
    assemble_tok<<<BLDM/256, 256>>>(cls, pos);
    cudaMemsetAsync(p_res, 0, (size_t)BLDM*sizeof(float));

    for (int lyr = 0; lyr < 24; lyr++) {
        resnorm_kernel<<<BL,256>>>(ln_w + (size_t)lyr*DM);

        // xz = xn @ w_in^T  (2052 x 3072, Kext=2304)
        cvt_ext<<<cdiv((size_t)2052*768,256),256>>>(p_xn, ae_xn, 2052, 768, 768, 768, 0);
        gemm_mma<<<dim3(24,17,1),256,GEMM_SMEM>>>(
            ae_xn, 2304, 0,
            we_in + (size_t)lyr*3072*2304, 2304, 0,
            p_xz, 3072, 0,
            BL, 3072, 2304, nullptr, 0, 1, 0);

        conv_silu<<<cdiv((size_t)2*BLDI,256),256>>>(
            conv_w + (size_t)lyr*2*DI*4, conv_b + (size_t)lyr*2*DI);

        // dbl = c @ w_x^T  (2 batches, 2052 x 80, Kext=4608, split-K=4)
        cvt_ext<<<cdiv((size_t)4104*1536,256),256>>>(p_c, ae_c, 4104, 1536, 1536, 1536, 0);
        cudaMemsetAsync(p_dbl, 0, (size_t)2*DBL80*sizeof(float));
        gemm_mma<<<dim3(1,17,8),256,GEMM_SMEM>>>(
            ae_c, 4608, (size_t)2052*4608,
            we_x + (size_t)lyr*2*80*4608, 4608, (size_t)80*4608,
            p_dbl, 80, (size_t)DBL80,
            BL, 80, 4608, nullptr, 0, 4, 0);

        // dt = softplus(dbl[:, :48] @ w_dt^T + b_dt)  (2 batches, Kext=192)
        cvt_ext<<<cdiv((size_t)4104*64,256),256>>>(p_dbl, ae_dt, 4104, 48, 64, 80, 0);
        gemm_mma<<<dim3(12,17,2),256,GEMM_SMEM>>>(
            ae_dt, 192, (size_t)2052*192,
            we_dt + (size_t)lyr*2*1536*192, 192, (size_t)1536*192,
            p_dt, DI, (size_t)BLDI,
            BL, DI, 192,
            b_dt + (size_t)lyr*2*DI, DI, 1, 1);

        cudaMemsetAsync(p_y, 0, (size_t)BLDI*sizeof(float));
        ssm_scan_kernel<<<dim3(12,4,2),128>>>(a_log, dd, lyr);

        // h = y @ w_out^T  (2052 x 768, Kext=4608)
        cvt_ext<<<cdiv((size_t)2052*1536,256),256>>>(p_y, ae_y, 2052, 1536, 1536, 1536, 0);
        gemm_mma<<<dim3(6,17,1),256,GEMM_SMEM>>>(
            ae_y, 4608, 0,
            we_out + (size_t)lyr*768*4608, 4608, 0,
            p_h, DM, 0,
            BL, DM, 4608, nullptr, 0, 1, 0);
    }

    final_ln<<<4,256>>>(fn_w, fn_b, out);
}